// round 2
// baseline (speedup 1.0000x reference)
#include <cuda_runtime.h>
#include <stdint.h>
#include <math.h>

// Problem constants (fixed by the reference)
#define N_NODES     4096
#define WORDS       128          // 4096 / 32 bits
#define IN_DIM      1024
#define HIDDEN      128
#define NUM_CLASSES 10
#define N_EDGES     65536
#define FINAL_DIM   896          // (2^(K+1)-1)*HIDDEN, K=2

// ---------------------------------------------------------------------------
// Scratch (device globals — no runtime allocation allowed)
// ---------------------------------------------------------------------------
__device__ unsigned int g_Abits [N_NODES * WORDS];   // 2 MB  adjacency bitmap (dedup'd)
__device__ unsigned int g_A2bits[N_NODES * WORDS];   // 2 MB  2-hop mask bitmap
__device__ float g_d1[N_NODES];                      // D^-1/2 for A
__device__ float g_d2[N_NODES];                      // D^-1/2 for A2
__device__ float g_R0[N_NODES * HIDDEN];             // 2 MB  relu(X@We + be)
__device__ float g_R1[N_NODES * 2 * HIDDEN];         // 4 MB  [A1@R0 | A2@R0]
__device__ float g_R2[N_NODES * 4 * HIDDEN];         // 8 MB  [A1@R1 | A2@R1]

// ---------------------------------------------------------------------------
// 1. zero the adjacency bitmap (A2bits is fully overwritten later)
// ---------------------------------------------------------------------------
__global__ void k_zero_bits() {
    int idx = blockIdx.x * blockDim.x + threadIdx.x;
    if (idx < N_NODES * WORDS) g_Abits[idx] = 0u;
}

// ---------------------------------------------------------------------------
// 2. scatter edges: A[src, dst] = 1 (set semantics via atomicOr on bitmap)
//    edge_index is INT32 (jax downgrades int64 without x64 mode).
// ---------------------------------------------------------------------------
__global__ void k_scatter(const int* __restrict__ e) {
    int i = blockIdx.x * blockDim.x + threadIdx.x;
    if (i < N_EDGES) {
        int s = e[i]           & (N_NODES - 1);   // mask is identity on valid data
        int d = e[N_EDGES + i] & (N_NODES - 1);
        atomicOr(&g_Abits[s * WORDS + (d >> 5)], 1u << (d & 31));
    }
}

// ---------------------------------------------------------------------------
// 3. degree of A + d1 = (deg + 1e-8)^-1/2.  One warp per row.
// ---------------------------------------------------------------------------
__global__ void k_deg1() {
    int row  = blockIdx.x * 8 + (threadIdx.x >> 5);
    int lane = threadIdx.x & 31;
    int cnt = 0;
    #pragma unroll
    for (int w = lane; w < WORDS; w += 32) cnt += __popc(g_Abits[row * WORDS + w]);
    #pragma unroll
    for (int o = 16; o; o >>= 1) cnt += __shfl_xor_sync(0xffffffffu, cnt, o);
    if (lane == 0) g_d1[row] = rsqrtf((float)cnt + 1e-8f);
}

// ---------------------------------------------------------------------------
// 4. 2-hop mask:  mask[i,k] = ( (#paths i->j->k) - A[i,k] - (i==k) ) > 0
//    One block (256 thr) per row i; path counts in shared memory.
// ---------------------------------------------------------------------------
#define MAXDEG 512
__global__ void k_twohop() {
    __shared__ unsigned int s_cnt[N_NODES];   // 16 KB
    __shared__ int s_jlist[MAXDEG];
    __shared__ int s_nj;
    __shared__ int s_deg2;

    const int row = blockIdx.x;
    const int tid = threadIdx.x;
    const int T   = 256;

    for (int i = tid; i < N_NODES; i += T) s_cnt[i] = 0u;
    if (tid == 0) { s_nj = 0; s_deg2 = 0; }
    __syncthreads();

    // extract out-neighbors j of row i
    for (int w = tid; w < WORDS; w += T) {
        unsigned word = g_Abits[row * WORDS + w];
        while (word) {
            int b = __ffs(word) - 1; word &= word - 1;
            int p = atomicAdd(&s_nj, 1);
            if (p < MAXDEG) s_jlist[p] = w * 32 + b;
        }
    }
    __syncthreads();

    // count paths: for each j in N(i), for each k in N(j): cnt[k]++
    int nj = min(s_nj, MAXDEG);
    int tasks = nj * WORDS;
    for (int t = tid; t < tasks; t += T) {
        int j = s_jlist[t >> 7];     // t / WORDS
        int w = t & (WORDS - 1);
        unsigned word = g_Abits[j * WORDS + w];
        int base = w * 32;
        while (word) {
            int b = __ffs(word) - 1; word &= word - 1;
            atomicAdd(&s_cnt[base + b], 1u);
        }
    }
    __syncthreads();

    // build mask bitmap + deg2
    for (int w = tid; w < WORDS; w += T) {
        unsigned my  = g_Abits[row * WORDS + w];
        unsigned out = 0u;
        #pragma unroll 8
        for (int b = 0; b < 32; b++) {
            int k = w * 32 + b;
            unsigned thr = ((my >> b) & 1u) + (k == row ? 1u : 0u);
            if (s_cnt[k] > thr) out |= (1u << b);
        }
        g_A2bits[row * WORDS + w] = out;
        if (out) atomicAdd(&s_deg2, __popc(out));
    }
    __syncthreads();
    if (tid == 0) g_d2[row] = rsqrtf((float)s_deg2 + 1e-8f);
}

// ---------------------------------------------------------------------------
// 5. Embed GEMM: R0 = relu(X[4096,1024] @ We[1024,128] + be)
//    fp32 tiled SIMT GEMM, BM=32, BN=128, BK=16, 128 threads, TM=8 TN=4.
// ---------------------------------------------------------------------------
__global__ void k_embed(const float* __restrict__ X, const float* __restrict__ W,
                        const float* __restrict__ bias) {
    __shared__ float As[16][32];    // [k][m]
    __shared__ float Bs[16][128];   // [k][n]

    const int bm  = blockIdx.x * 32;
    const int tid = threadIdx.x;          // 128 threads
    const int tx  = tid & 31;             // col group: cols tx*4 .. tx*4+3
    const int ty  = tid >> 5;             // row group: rows ty*8 .. ty*8+7

    float acc[8][4];
    #pragma unroll
    for (int m = 0; m < 8; m++)
        #pragma unroll
        for (int n = 0; n < 4; n++) acc[m][n] = 0.f;

    for (int k0 = 0; k0 < IN_DIM; k0 += 16) {
        // load A tile 32x16 (one float4 per thread), transpose into As[k][m]
        {
            int r  = tid >> 2;        // 0..31
            int c4 = tid & 3;         // 0..3
            float4 v = *(const float4*)(X + (size_t)(bm + r) * IN_DIM + k0 + c4 * 4);
            As[c4 * 4 + 0][r] = v.x;
            As[c4 * 4 + 1][r] = v.y;
            As[c4 * 4 + 2][r] = v.z;
            As[c4 * 4 + 3][r] = v.w;
        }
        // load B tile 16x128 (four float4 per thread)
        #pragma unroll
        for (int l = 0; l < 4; l++) {
            int idx = l * 128 + tid;      // 0..511 float4 slots
            int r   = idx >> 5;           // 0..15
            int c4  = idx & 31;           // 0..31
            *(float4*)&Bs[r][c4 * 4] = *(const float4*)(W + (size_t)(k0 + r) * HIDDEN + c4 * 4);
        }
        __syncthreads();

        #pragma unroll
        for (int kk = 0; kk < 16; kk++) {
            float a[8];
            float4 b4 = *(const float4*)&Bs[kk][tx * 4];
            float bb[4] = { b4.x, b4.y, b4.z, b4.w };
            #pragma unroll
            for (int m = 0; m < 8; m++) a[m] = As[kk][ty * 8 + m];
            #pragma unroll
            for (int m = 0; m < 8; m++)
                #pragma unroll
                for (int n = 0; n < 4; n++) acc[m][n] += a[m] * bb[n];
        }
        __syncthreads();
    }

    #pragma unroll
    for (int m = 0; m < 8; m++) {
        int row = bm + ty * 8 + m;
        #pragma unroll
        for (int n = 0; n < 4; n++) {
            int col = tx * 4 + n;
            float v = acc[m][n] + bias[col];
            g_R0[(size_t)row * HIDDEN + col] = v > 0.f ? v : 0.f;
        }
    }
}

// ---------------------------------------------------------------------------
// 6. spmm: out[i, off + c] = d[i] * sum_{k in bits[i]} d[k] * Rin[k, c]
//    One block per row, C threads (one per column).
// ---------------------------------------------------------------------------
template<int C>
__device__ __forceinline__ void spmm_body(const float* __restrict__ Rin,
                                          float* __restrict__ Rout,
                                          int outStride, int outOff,
                                          const unsigned int* __restrict__ bits,
                                          const float* __restrict__ dv) {
    const int row = blockIdx.x;
    const int c   = threadIdx.x;
    const unsigned int* brow = bits + (size_t)row * WORDS;
    float acc = 0.f;
    #pragma unroll 4
    for (int w = 0; w < WORDS; w++) {
        unsigned word = brow[w];
        int base = w * 32;
        while (word) {
            int b = __ffs(word) - 1; word &= word - 1;
            int k = base + b;
            acc += dv[k] * Rin[(size_t)k * C + c];
        }
    }
    Rout[(size_t)row * outStride + outOff + c] = dv[row] * acc;
}

__global__ void k_spmm_1_a1() { spmm_body<128>(g_R0, g_R1, 256,   0, g_Abits,  g_d1); }
__global__ void k_spmm_1_a2() { spmm_body<128>(g_R0, g_R1, 256, 128, g_A2bits, g_d2); }
__global__ void k_spmm_2_a1() { spmm_body<256>(g_R1, g_R2, 512,   0, g_Abits,  g_d1); }
__global__ void k_spmm_2_a2() { spmm_body<256>(g_R1, g_R2, 512, 256, g_A2bits, g_d2); }

// ---------------------------------------------------------------------------
// 7. classifier: out[4096,10] = concat(R0,R1,R2) @ Wc + bc.  Warp per row.
// ---------------------------------------------------------------------------
__global__ void k_final(const float* __restrict__ Wc, const float* __restrict__ bc,
                        float* __restrict__ out) {
    int row  = blockIdx.x * 8 + (threadIdx.x >> 5);
    int lane = threadIdx.x & 31;

    float acc[NUM_CLASSES];
    #pragma unroll
    for (int cc = 0; cc < NUM_CLASSES; cc++) acc[cc] = 0.f;

    for (int j = lane; j < FINAL_DIM; j += 32) {
        float x;
        if (j < 128)       x = g_R0[(size_t)row * 128 + j];
        else if (j < 384)  x = g_R1[(size_t)row * 256 + (j - 128)];
        else               x = g_R2[(size_t)row * 512 + (j - 384)];
        const float* wr = Wc + (size_t)j * NUM_CLASSES;
        #pragma unroll
        for (int cc = 0; cc < NUM_CLASSES; cc++) acc[cc] += x * wr[cc];
    }
    #pragma unroll
    for (int cc = 0; cc < NUM_CLASSES; cc++)
        #pragma unroll
        for (int o = 16; o; o >>= 1) acc[cc] += __shfl_xor_sync(0xffffffffu, acc[cc], o);

    if (lane == 0) {
        #pragma unroll
        for (int cc = 0; cc < NUM_CLASSES; cc++)
            out[(size_t)row * NUM_CLASSES + cc] = acc[cc] + bc[cc];
    }
}

// ---------------------------------------------------------------------------
// launch
// ---------------------------------------------------------------------------
extern "C" void kernel_launch(void* const* d_in, const int* in_sizes, int n_in,
                              void* d_out, int out_size) {
    const float* X  = (const float*)d_in[0];
    const int*   E  = (const int*)d_in[1];          // int32! (jax x64 disabled)
    const float* We = (const float*)d_in[2];
    const float* be = (const float*)d_in[3];
    const float* Wc = (const float*)d_in[4];
    const float* bc = (const float*)d_in[5];
    float* out = (float*)d_out;

    k_zero_bits<<<(N_NODES * WORDS + 255) / 256, 256>>>();
    k_scatter<<<N_EDGES / 256, 256>>>(E);
    k_deg1<<<N_NODES / 8, 256>>>();
    k_twohop<<<N_NODES, 256>>>();

    k_embed<<<N_NODES / 32, 128>>>(X, We, be);

    k_spmm_1_a1<<<N_NODES, 128>>>();
    k_spmm_1_a2<<<N_NODES, 128>>>();
    k_spmm_2_a1<<<N_NODES, 256>>>();
    k_spmm_2_a2<<<N_NODES, 256>>>();

    k_final<<<N_NODES / 8, 256>>>(Wc, bc, out);
}

// round 4
// speedup vs baseline: 2.0226x; 2.0226x over previous
#include <cuda_runtime.h>
#include <stdint.h>
#include <math.h>

#define N_NODES     4096
#define WORDS       128
#define IN_DIM      1024
#define HIDDEN      128
#define NUM_CLASSES 10
#define N_EDGES     65536
#define FINAL_DIM   896
#define CAP1        128
#define CAP2        768

// ---------------------------------------------------------------------------
// Scratch (device globals — no runtime allocation allowed)
// ---------------------------------------------------------------------------
__device__ unsigned int g_Abits [N_NODES * WORDS];   // 2 MB
__device__ unsigned int g_A2bits[N_NODES * WORDS];   // 2 MB
__device__ float g_d1[N_NODES];
__device__ float g_d2[N_NODES];
__device__ unsigned short g_idx1[N_NODES * CAP1];    // 1 MB   CSR for A
__device__ unsigned short g_idx2[N_NODES * CAP2];    // 6 MB   CSR for A2
__device__ int   g_cnt1[N_NODES];
__device__ int   g_cnt2[N_NODES];
__device__ float g_R0[N_NODES * HIDDEN];             // 2 MB
__device__ float g_R1[N_NODES * 2 * HIDDEN];         // 4 MB
__device__ float g_R2[N_NODES * 4 * HIDDEN];         // 8 MB

// ---------------------------------------------------------------------------
// 1. zero adjacency bitmap
// ---------------------------------------------------------------------------
__global__ void k_zero_bits() {
    int idx = blockIdx.x * blockDim.x + threadIdx.x;
    if (idx < N_NODES * WORDS) g_Abits[idx] = 0u;
}

// ---------------------------------------------------------------------------
// 2. scatter edges (edge_index is int32 — jax x64 disabled)
// ---------------------------------------------------------------------------
__global__ void k_scatter(const int* __restrict__ e) {
    int i = blockIdx.x * blockDim.x + threadIdx.x;
    if (i < N_EDGES) {
        int s = e[i]           & (N_NODES - 1);
        int d = e[N_EDGES + i] & (N_NODES - 1);
        atomicOr(&g_Abits[s * WORDS + (d >> 5)], 1u << (d & 31));
    }
}

// ---------------------------------------------------------------------------
// 3. 2-hop mask:  mask[i,k] = ((#paths i->j->k) - A[i,k] - (i==k)) > 0
// ---------------------------------------------------------------------------
#define MAXDEG 512
__global__ void k_twohop() {
    __shared__ unsigned int s_cnt[N_NODES];   // 16 KB
    __shared__ int s_jlist[MAXDEG];
    __shared__ int s_nj;

    const int row = blockIdx.x;
    const int tid = threadIdx.x;
    const int T   = 256;

    for (int i = tid; i < N_NODES; i += T) s_cnt[i] = 0u;
    if (tid == 0) s_nj = 0;
    __syncthreads();

    for (int w = tid; w < WORDS; w += T) {
        unsigned word = g_Abits[row * WORDS + w];
        while (word) {
            int b = __ffs(word) - 1; word &= word - 1;
            int p = atomicAdd(&s_nj, 1);
            if (p < MAXDEG) s_jlist[p] = w * 32 + b;
        }
    }
    __syncthreads();

    int nj = min(s_nj, MAXDEG);
    int tasks = nj * WORDS;
    for (int t = tid; t < tasks; t += T) {
        int j = s_jlist[t >> 7];
        int w = t & (WORDS - 1);
        unsigned word = g_Abits[j * WORDS + w];
        int base = w * 32;
        while (word) {
            int b = __ffs(word) - 1; word &= word - 1;
            atomicAdd(&s_cnt[base + b], 1u);
        }
    }
    __syncthreads();

    for (int w = tid; w < WORDS; w += T) {
        unsigned my  = g_Abits[row * WORDS + w];
        unsigned out = 0u;
        #pragma unroll 8
        for (int b = 0; b < 32; b++) {
            int k = w * 32 + b;
            unsigned thr = ((my >> b) & 1u) + (k == row ? 1u : 0u);
            if (s_cnt[k] > thr) out |= (1u << b);
        }
        g_A2bits[row * WORDS + w] = out;
    }
}

// ---------------------------------------------------------------------------
// 4. bitmap -> CSR (u16 indices) + degree -> d = (deg+1e-8)^-1/2
//    One warp per row; lane owns 4 contiguous words; warp-scan for offsets.
// ---------------------------------------------------------------------------
__device__ __forceinline__ void extract_body(const unsigned int* __restrict__ bits,
                                             unsigned short* __restrict__ idxOut,
                                             int* __restrict__ cntOut,
                                             float* __restrict__ dOut, int cap) {
    int row  = blockIdx.x * 8 + (threadIdx.x >> 5);
    int lane = threadIdx.x & 31;
    const unsigned int* brow = bits + (size_t)row * WORDS;

    unsigned w[4]; int c = 0;
    #pragma unroll
    for (int u = 0; u < 4; u++) { w[u] = brow[lane * 4 + u]; c += __popc(w[u]); }

    // inclusive warp scan of c
    int inc = c;
    #pragma unroll
    for (int o = 1; o < 32; o <<= 1) {
        int t = __shfl_up_sync(0xffffffffu, inc, o);
        if (lane >= o) inc += t;
    }
    int total = __shfl_sync(0xffffffffu, inc, 31);
    int p = inc - c;   // exclusive offset

    unsigned short* dst = idxOut + (size_t)row * cap;
    #pragma unroll
    for (int u = 0; u < 4; u++) {
        unsigned word = w[u];
        int base = (lane * 4 + u) * 32;
        while (word) {
            int b = __ffs(word) - 1; word &= word - 1;
            if (p < cap) dst[p] = (unsigned short)(base + b);
            p++;
        }
    }
    if (lane == 31) {
        cntOut[row] = min(total, cap);
        dOut[row]   = rsqrtf((float)total + 1e-8f);
    }
}

__global__ void k_extract1() { extract_body(g_Abits,  g_idx1, g_cnt1, g_d1, CAP1); }
__global__ void k_extract2() { extract_body(g_A2bits, g_idx2, g_cnt2, g_d2, CAP2); }

// ---------------------------------------------------------------------------
// 5. Embed GEMM: R0 = relu(X @ We + be), fp32 SIMT tiled
// ---------------------------------------------------------------------------
__global__ void k_embed(const float* __restrict__ X, const float* __restrict__ W,
                        const float* __restrict__ bias) {
    __shared__ float As[16][32];
    __shared__ float Bs[16][128];

    const int bm  = blockIdx.x * 32;
    const int tid = threadIdx.x;
    const int tx  = tid & 31;
    const int ty  = tid >> 5;

    float acc[8][4];
    #pragma unroll
    for (int m = 0; m < 8; m++)
        #pragma unroll
        for (int n = 0; n < 4; n++) acc[m][n] = 0.f;

    for (int k0 = 0; k0 < IN_DIM; k0 += 16) {
        {
            int r  = tid >> 2;
            int c4 = tid & 3;
            float4 v = *(const float4*)(X + (size_t)(bm + r) * IN_DIM + k0 + c4 * 4);
            As[c4 * 4 + 0][r] = v.x;
            As[c4 * 4 + 1][r] = v.y;
            As[c4 * 4 + 2][r] = v.z;
            As[c4 * 4 + 3][r] = v.w;
        }
        #pragma unroll
        for (int l = 0; l < 4; l++) {
            int idx = l * 128 + tid;
            int r   = idx >> 5;
            int c4  = idx & 31;
            *(float4*)&Bs[r][c4 * 4] = *(const float4*)(W + (size_t)(k0 + r) * HIDDEN + c4 * 4);
        }
        __syncthreads();

        #pragma unroll
        for (int kk = 0; kk < 16; kk++) {
            float a[8];
            float4 b4 = *(const float4*)&Bs[kk][tx * 4];
            float bb[4] = { b4.x, b4.y, b4.z, b4.w };
            #pragma unroll
            for (int m = 0; m < 8; m++) a[m] = As[kk][ty * 8 + m];
            #pragma unroll
            for (int m = 0; m < 8; m++)
                #pragma unroll
                for (int n = 0; n < 4; n++) acc[m][n] += a[m] * bb[n];
        }
        __syncthreads();
    }

    #pragma unroll
    for (int m = 0; m < 8; m++) {
        int row = bm + ty * 8 + m;
        #pragma unroll
        for (int n = 0; n < 4; n++) {
            int col = tx * 4 + n;
            float v = acc[m][n] + bias[col];
            g_R0[(size_t)row * HIDDEN + col] = v > 0.f ? v : 0.f;
        }
    }
}

// ---------------------------------------------------------------------------
// 6. CSR spmm:  out[i, off+c] = d[i] * sum_e d[k_e] * Rin[k_e, c]
//    One block per row; neighbor ids+weights staged in smem; 8-way MLP.
// ---------------------------------------------------------------------------
template<int C, int CAP>
__device__ __forceinline__ void spmm_csr(const float* __restrict__ Rin,
                                         float* __restrict__ Rout,
                                         int outStride, int outOff,
                                         const unsigned short* __restrict__ idx,
                                         const int* __restrict__ cnt,
                                         const float* __restrict__ dv) {
    __shared__ unsigned short s_idx[CAP];
    __shared__ float          s_w[CAP];

    const int row = blockIdx.x;
    const int c   = threadIdx.x;
    const int n   = cnt[row];
    const unsigned short* src = idx + (size_t)row * CAP;

    for (int e = c; e < n; e += C) {
        int k = src[e];
        s_idx[e] = (unsigned short)k;
        s_w[e]   = dv[k];
    }
    __syncthreads();

    float acc = 0.f;
    int e = 0;
    for (; e + 8 <= n; e += 8) {
        #pragma unroll
        for (int u = 0; u < 8; u++) {
            int k = s_idx[e + u];
            acc += s_w[e + u] * Rin[(size_t)k * C + c];
        }
    }
    for (; e < n; e++) {
        int k = s_idx[e];
        acc += s_w[e] * Rin[(size_t)k * C + c];
    }
    Rout[(size_t)row * outStride + outOff + c] = dv[row] * acc;
}

__global__ void k_spmm_1_a1() { spmm_csr<128, CAP1>(g_R0, g_R1, 256,   0, g_idx1, g_cnt1, g_d1); }
__global__ void k_spmm_1_a2() { spmm_csr<128, CAP2>(g_R0, g_R1, 256, 128, g_idx2, g_cnt2, g_d2); }
__global__ void k_spmm_2_a1() { spmm_csr<256, CAP1>(g_R1, g_R2, 512,   0, g_idx1, g_cnt1, g_d1); }
__global__ void k_spmm_2_a2() { spmm_csr<256, CAP2>(g_R1, g_R2, 512, 256, g_idx2, g_cnt2, g_d2); }

// ---------------------------------------------------------------------------
// 7. classifier
// ---------------------------------------------------------------------------
__global__ void k_final(const float* __restrict__ Wc, const float* __restrict__ bc,
                        float* __restrict__ out) {
    int row  = blockIdx.x * 8 + (threadIdx.x >> 5);
    int lane = threadIdx.x & 31;

    float acc[NUM_CLASSES];
    #pragma unroll
    for (int cc = 0; cc < NUM_CLASSES; cc++) acc[cc] = 0.f;

    for (int j = lane; j < FINAL_DIM; j += 32) {
        float x;
        if (j < 128)       x = g_R0[(size_t)row * 128 + j];
        else if (j < 384)  x = g_R1[(size_t)row * 256 + (j - 128)];
        else               x = g_R2[(size_t)row * 512 + (j - 384)];
        const float* wr = Wc + (size_t)j * NUM_CLASSES;
        #pragma unroll
        for (int cc = 0; cc < NUM_CLASSES; cc++) acc[cc] += x * wr[cc];
    }
    #pragma unroll
    for (int cc = 0; cc < NUM_CLASSES; cc++)
        #pragma unroll
        for (int o = 16; o; o >>= 1) acc[cc] += __shfl_xor_sync(0xffffffffu, acc[cc], o);

    if (lane == 0) {
        #pragma unroll
        for (int cc = 0; cc < NUM_CLASSES; cc++)
            out[(size_t)row * NUM_CLASSES + cc] = acc[cc] + bc[cc];
    }
}

// ---------------------------------------------------------------------------
// launch — pure kernel launches, nothing else
// ---------------------------------------------------------------------------
extern "C" void kernel_launch(void* const* d_in, const int* in_sizes, int n_in,
                              void* d_out, int out_size) {
    const float* X  = (const float*)d_in[0];
    const int*   E  = (const int*)d_in[1];          // int32 (jax x64 disabled)
    const float* We = (const float*)d_in[2];
    const float* be = (const float*)d_in[3];
    const float* Wc = (const float*)d_in[4];
    const float* bc = (const float*)d_in[5];
    float* out = (float*)d_out;

    // graph prep
    k_zero_bits<<<(N_NODES * WORDS + 255) / 256, 256>>>();
    k_scatter<<<N_EDGES / 256, 256>>>(E);
    k_twohop<<<N_NODES, 256>>>();
    k_extract1<<<N_NODES / 8, 256>>>();
    k_extract2<<<N_NODES / 8, 256>>>();

    // embed
    k_embed<<<N_NODES / 32, 128>>>(X, We, be);

    // propagation
    k_spmm_1_a1<<<N_NODES, 128>>>();
    k_spmm_1_a2<<<N_NODES, 128>>>();
    k_spmm_2_a1<<<N_NODES, 256>>>();
    k_spmm_2_a2<<<N_NODES, 256>>>();

    // classifier
    k_final<<<N_NODES / 8, 256>>>(Wc, bc, out);
}

// round 5
// speedup vs baseline: 2.1310x; 1.0536x over previous
#include <cuda_runtime.h>
#include <cuda_fp16.h>
#include <stdint.h>
#include <math.h>

#define N_NODES     4096
#define WORDS       128
#define IN_DIM      1024
#define HIDDEN      128
#define NUM_CLASSES 10
#define N_EDGES     65536
#define FINAL_DIM   896
#define CAP1        128
#define CAP2        768

// ---------------------------------------------------------------------------
// Scratch (device globals — no runtime allocation allowed)
// ---------------------------------------------------------------------------
__device__ unsigned int g_Abits [N_NODES * WORDS];   // 2 MB
__device__ unsigned int g_A2bits[N_NODES * WORDS];   // 2 MB
__device__ float g_d1[N_NODES];
__device__ float g_d2[N_NODES];
__device__ unsigned short g_idx1[N_NODES * CAP1];    // 1 MB   CSR for A
__device__ unsigned short g_idx2[N_NODES * CAP2];    // 6 MB   CSR for A2
__device__ int   g_cnt1[N_NODES];
__device__ int   g_cnt2[N_NODES];
__device__ float g_R0[N_NODES * HIDDEN];             // 2 MB  fp32 (classifier)
__device__ float g_R1[N_NODES * 2 * HIDDEN];         // 4 MB  fp32 (classifier)
__device__ float g_R2[N_NODES * 4 * HIDDEN];         // 8 MB  fp32 (classifier)
__device__ __half g_H0[N_NODES * HIDDEN];            // 1 MB  fp16 spmm operand
__device__ __half g_H1[N_NODES * 2 * HIDDEN];        // 2 MB  fp16 spmm operand

// ---------------------------------------------------------------------------
// 1. zero adjacency bitmap
// ---------------------------------------------------------------------------
__global__ void k_zero_bits() {
    int idx = blockIdx.x * blockDim.x + threadIdx.x;
    if (idx < N_NODES * WORDS) g_Abits[idx] = 0u;
}

// ---------------------------------------------------------------------------
// 2. scatter edges (edge_index is int32 — jax x64 disabled)
// ---------------------------------------------------------------------------
__global__ void k_scatter(const int* __restrict__ e) {
    int i = blockIdx.x * blockDim.x + threadIdx.x;
    if (i < N_EDGES) {
        int s = e[i]           & (N_NODES - 1);
        int d = e[N_EDGES + i] & (N_NODES - 1);
        atomicOr(&g_Abits[s * WORDS + (d >> 5)], 1u << (d & 31));
    }
}

// ---------------------------------------------------------------------------
// 3. bitmap -> CSR (u16 indices) + degree -> d = (deg+1e-8)^-1/2
//    One warp per row; lane owns 4 contiguous words; warp-scan for offsets.
// ---------------------------------------------------------------------------
__device__ __forceinline__ void extract_body(const unsigned int* __restrict__ bits,
                                             unsigned short* __restrict__ idxOut,
                                             int* __restrict__ cntOut,
                                             float* __restrict__ dOut, int cap) {
    int row  = blockIdx.x * 8 + (threadIdx.x >> 5);
    int lane = threadIdx.x & 31;
    const unsigned int* brow = bits + (size_t)row * WORDS;

    unsigned w[4]; int c = 0;
    #pragma unroll
    for (int u = 0; u < 4; u++) { w[u] = brow[lane * 4 + u]; c += __popc(w[u]); }

    int inc = c;
    #pragma unroll
    for (int o = 1; o < 32; o <<= 1) {
        int t = __shfl_up_sync(0xffffffffu, inc, o);
        if (lane >= o) inc += t;
    }
    int total = __shfl_sync(0xffffffffu, inc, 31);
    int p = inc - c;

    unsigned short* dst = idxOut + (size_t)row * cap;
    #pragma unroll
    for (int u = 0; u < 4; u++) {
        unsigned word = w[u];
        int base = (lane * 4 + u) * 32;
        while (word) {
            int b = __ffs(word) - 1; word &= word - 1;
            if (p < cap) dst[p] = (unsigned short)(base + b);
            p++;
        }
    }
    if (lane == 31) {
        cntOut[row] = min(total, cap);
        dOut[row]   = rsqrtf((float)total + 1e-8f);
    }
}

__global__ void k_extract1() { extract_body(g_Abits,  g_idx1, g_cnt1, g_d1, CAP1); }
__global__ void k_extract2() { extract_body(g_A2bits, g_idx2, g_cnt2, g_d2, CAP2); }

// ---------------------------------------------------------------------------
// 4. 2-hop mask via neighbor-row UNION + exact counts at special positions.
//    cnt[k] > A[i,k] + (i==k):
//      k not neighbor, k!=i : >=1 path  <=> bit in union of neighbor rows
//      k neighbor or k==i   : exact count vs threshold (<= deg+1 positions)
//    One block (128 thr) per row; requires g_idx1/g_cnt1 (k_extract1 first).
// ---------------------------------------------------------------------------
__global__ void k_twohop() {
    __shared__ unsigned s_out[WORDS];
    __shared__ unsigned short s_nb[CAP1];

    const int row = blockIdx.x;
    const int tid = threadIdx.x;   // 128
    const int nj  = g_cnt1[row];

    if (tid < nj) s_nb[tid] = g_idx1[(size_t)row * CAP1 + tid];
    __syncthreads();

    // union of neighbor rows (thread owns word `tid`)
    unsigned u = 0;
    for (int e = 0; e < nj; e++) {
        int j = s_nb[e];
        u |= g_Abits[(size_t)j * WORDS + tid];
    }
    unsigned my   = g_Abits[(size_t)row * WORDS + tid];
    unsigned diag = ((row >> 5) == tid) ? (1u << (row & 31)) : 0u;
    s_out[tid] = u & ~my & ~diag;
    __syncthreads();

    // special positions: neighbors of row, plus row itself
    if (tid <= nj) {
        int k = (tid < nj) ? s_nb[tid] : row;
        int w = k >> 5, b = k & 31;
        int cnt = 0;
        for (int e = 0; e < nj; e++) {
            int j = s_nb[e];
            cnt += (g_Abits[(size_t)j * WORDS + w] >> b) & 1;
        }
        int abit = (g_Abits[(size_t)row * WORDS + w] >> b) & 1;
        int thr  = abit + (k == row ? 1 : 0);
        if (cnt > thr) atomicOr(&s_out[w], 1u << b);
    }
    __syncthreads();
    g_A2bits[(size_t)row * WORDS + tid] = s_out[tid];
}

// ---------------------------------------------------------------------------
// 5. Embed GEMM: R0 = relu(X @ We + be), fp32 SIMT tiled; writes fp32 + fp16
// ---------------------------------------------------------------------------
__global__ void k_embed(const float* __restrict__ X, const float* __restrict__ W,
                        const float* __restrict__ bias) {
    __shared__ float As[16][32];
    __shared__ float Bs[16][128];

    const int bm  = blockIdx.x * 32;
    const int tid = threadIdx.x;
    const int tx  = tid & 31;
    const int ty  = tid >> 5;

    float acc[8][4];
    #pragma unroll
    for (int m = 0; m < 8; m++)
        #pragma unroll
        for (int n = 0; n < 4; n++) acc[m][n] = 0.f;

    for (int k0 = 0; k0 < IN_DIM; k0 += 16) {
        {
            int r  = tid >> 2;
            int c4 = tid & 3;
            float4 v = *(const float4*)(X + (size_t)(bm + r) * IN_DIM + k0 + c4 * 4);
            As[c4 * 4 + 0][r] = v.x;
            As[c4 * 4 + 1][r] = v.y;
            As[c4 * 4 + 2][r] = v.z;
            As[c4 * 4 + 3][r] = v.w;
        }
        #pragma unroll
        for (int l = 0; l < 4; l++) {
            int idx = l * 128 + tid;
            int r   = idx >> 5;
            int c4  = idx & 31;
            *(float4*)&Bs[r][c4 * 4] = *(const float4*)(W + (size_t)(k0 + r) * HIDDEN + c4 * 4);
        }
        __syncthreads();

        #pragma unroll
        for (int kk = 0; kk < 16; kk++) {
            float a[8];
            float4 b4 = *(const float4*)&Bs[kk][tx * 4];
            float bb[4] = { b4.x, b4.y, b4.z, b4.w };
            #pragma unroll
            for (int m = 0; m < 8; m++) a[m] = As[kk][ty * 8 + m];
            #pragma unroll
            for (int m = 0; m < 8; m++)
                #pragma unroll
                for (int n = 0; n < 4; n++) acc[m][n] += a[m] * bb[n];
        }
        __syncthreads();
    }

    #pragma unroll
    for (int m = 0; m < 8; m++) {
        int row = bm + ty * 8 + m;
        #pragma unroll
        for (int n = 0; n < 4; n++) {
            int col = tx * 4 + n;
            float v = acc[m][n] + bias[col];
            v = v > 0.f ? v : 0.f;
            g_R0[(size_t)row * HIDDEN + col] = v;
            g_H0[(size_t)row * HIDDEN + col] = __float2half(v);
        }
    }
}

// ---------------------------------------------------------------------------
// 6. CSR spmm, fp16 operands, fp32 accumulate:
//    out[i, off+c] = d[i] * sum_e d[k_e] * Hin[k_e, c]
// ---------------------------------------------------------------------------
template<int C, int CAP, bool WRITE_H>
__device__ __forceinline__ void spmm_csr(const __half* __restrict__ Hin,
                                         float* __restrict__ RoutF,
                                         __half* __restrict__ RoutH,
                                         int outStride, int outOff,
                                         const unsigned short* __restrict__ idx,
                                         const int* __restrict__ cnt,
                                         const float* __restrict__ dv) {
    __shared__ unsigned short s_idx[CAP];
    __shared__ float          s_w[CAP];

    const int row = blockIdx.x;
    const int c   = threadIdx.x;
    const int n   = cnt[row];
    const unsigned short* src = idx + (size_t)row * CAP;

    for (int e = c; e < n; e += C) {
        int k = src[e];
        s_idx[e] = (unsigned short)k;
        s_w[e]   = dv[k];
    }
    __syncthreads();

    float acc = 0.f;
    int e = 0;
    for (; e + 8 <= n; e += 8) {
        #pragma unroll
        for (int u = 0; u < 8; u++) {
            int k = s_idx[e + u];
            acc += s_w[e + u] * __half2float(Hin[(size_t)k * C + c]);
        }
    }
    for (; e < n; e++) {
        int k = s_idx[e];
        acc += s_w[e] * __half2float(Hin[(size_t)k * C + c]);
    }
    float val = dv[row] * acc;
    RoutF[(size_t)row * outStride + outOff + c] = val;
    if (WRITE_H)
        RoutH[(size_t)row * outStride + outOff + c] = __float2half(val);
}

__global__ void k_spmm_1_a1() { spmm_csr<128, CAP1, true >(g_H0, g_R1, g_H1, 256,   0, g_idx1, g_cnt1, g_d1); }
__global__ void k_spmm_1_a2() { spmm_csr<128, CAP2, true >(g_H0, g_R1, g_H1, 256, 128, g_idx2, g_cnt2, g_d2); }
__global__ void k_spmm_2_a1() { spmm_csr<256, CAP1, false>(g_H1, g_R2, (__half*)0, 512,   0, g_idx1, g_cnt1, g_d1); }
__global__ void k_spmm_2_a2() { spmm_csr<256, CAP2, false>(g_H1, g_R2, (__half*)0, 512, 256, g_idx2, g_cnt2, g_d2); }

// ---------------------------------------------------------------------------
// 7. classifier (reads fp32 feature buffers)
// ---------------------------------------------------------------------------
__global__ void k_final(const float* __restrict__ Wc, const float* __restrict__ bc,
                        float* __restrict__ out) {
    int row  = blockIdx.x * 8 + (threadIdx.x >> 5);
    int lane = threadIdx.x & 31;

    float acc[NUM_CLASSES];
    #pragma unroll
    for (int cc = 0; cc < NUM_CLASSES; cc++) acc[cc] = 0.f;

    for (int j = lane; j < FINAL_DIM; j += 32) {
        float x;
        if (j < 128)       x = g_R0[(size_t)row * 128 + j];
        else if (j < 384)  x = g_R1[(size_t)row * 256 + (j - 128)];
        else               x = g_R2[(size_t)row * 512 + (j - 384)];
        const float* wr = Wc + (size_t)j * NUM_CLASSES;
        #pragma unroll
        for (int cc = 0; cc < NUM_CLASSES; cc++) acc[cc] += x * wr[cc];
    }
    #pragma unroll
    for (int cc = 0; cc < NUM_CLASSES; cc++)
        #pragma unroll
        for (int o = 16; o; o >>= 1) acc[cc] += __shfl_xor_sync(0xffffffffu, acc[cc], o);

    if (lane == 0) {
        #pragma unroll
        for (int cc = 0; cc < NUM_CLASSES; cc++)
            out[(size_t)row * NUM_CLASSES + cc] = acc[cc] + bc[cc];
    }
}

// ---------------------------------------------------------------------------
// launch — pure kernel launches, nothing else
// ---------------------------------------------------------------------------
extern "C" void kernel_launch(void* const* d_in, const int* in_sizes, int n_in,
                              void* d_out, int out_size) {
    const float* X  = (const float*)d_in[0];
    const int*   E  = (const int*)d_in[1];          // int32 (jax x64 disabled)
    const float* We = (const float*)d_in[2];
    const float* be = (const float*)d_in[3];
    const float* Wc = (const float*)d_in[4];
    const float* bc = (const float*)d_in[5];
    float* out = (float*)d_out;

    // graph prep
    k_zero_bits<<<(N_NODES * WORDS + 255) / 256, 256>>>();
    k_scatter<<<N_EDGES / 256, 256>>>(E);
    k_extract1<<<N_NODES / 8, 256>>>();          // CSR for A (needed by twohop)
    k_twohop<<<N_NODES, 128>>>();                // union + special-count method
    k_extract2<<<N_NODES / 8, 256>>>();          // CSR for A2

    // embed
    k_embed<<<N_NODES / 32, 128>>>(X, We, be);

    // propagation (fp16 operands, fp32 accumulate)
    k_spmm_1_a1<<<N_NODES, 128>>>();
    k_spmm_1_a2<<<N_NODES, 128>>>();
    k_spmm_2_a1<<<N_NODES, 256>>>();
    k_spmm_2_a2<<<N_NODES, 256>>>();

    // classifier
    k_final<<<N_NODES / 8, 256>>>(Wc, bc, out);
}

// round 6
// speedup vs baseline: 3.1843x; 1.4943x over previous
#include <cuda_runtime.h>
#include <cuda_fp16.h>
#include <stdint.h>
#include <math.h>

#define N_NODES     4096
#define WORDS       128
#define IN_DIM      1024
#define HIDDEN      128
#define NUM_CLASSES 10
#define N_EDGES     65536
#define FINAL_DIM   896
#define CAP1        128
#define CAP2        768

// ---------------------------------------------------------------------------
// Scratch (device globals — no runtime allocation allowed)
// ---------------------------------------------------------------------------
__device__ unsigned int g_Abits [N_NODES * WORDS];   // 2 MB
__device__ unsigned int g_A2bits[N_NODES * WORDS];   // 2 MB
__device__ float g_d1[N_NODES];
__device__ float g_d2[N_NODES];
__device__ unsigned short g_idx1[N_NODES * CAP1];    // 1 MB
__device__ unsigned short g_idx2[N_NODES * CAP2];    // 6 MB
__device__ int   g_cnt1[N_NODES];
__device__ int   g_cnt2[N_NODES];
__device__ float g_R0[N_NODES * HIDDEN];             // 2 MB  fp32 (classifier)
__device__ float g_R1[N_NODES * 2 * HIDDEN];         // 4 MB  fp32 (classifier)
__device__ float g_R2[N_NODES * 4 * HIDDEN];         // 8 MB  fp32 (classifier)
// prescaled fp16 gather operands:  Pxa = d1[k]*R[k,:],  Pxb = d2[k]*R[k,:]
__device__ __half g_P0a[N_NODES * HIDDEN];           // 1 MB
__device__ __half g_P0b[N_NODES * HIDDEN];           // 1 MB
__device__ __half g_P1a[N_NODES * 2 * HIDDEN];       // 2 MB
__device__ __half g_P1b[N_NODES * 2 * HIDDEN];       // 2 MB

// ---------------------------------------------------------------------------
__global__ void k_zero_bits() {
    int idx = blockIdx.x * blockDim.x + threadIdx.x;
    if (idx < N_NODES * WORDS) g_Abits[idx] = 0u;
}

__global__ void k_scatter(const int* __restrict__ e) {
    int i = blockIdx.x * blockDim.x + threadIdx.x;
    if (i < N_EDGES) {
        int s = e[i]           & (N_NODES - 1);
        int d = e[N_EDGES + i] & (N_NODES - 1);
        atomicOr(&g_Abits[s * WORDS + (d >> 5)], 1u << (d & 31));
    }
}

// ---------------------------------------------------------------------------
// bitmap -> CSR (u16) + d = (deg+1e-8)^-1/2.  One warp per row.
// ---------------------------------------------------------------------------
__device__ __forceinline__ void extract_body(const unsigned int* __restrict__ bits,
                                             unsigned short* __restrict__ idxOut,
                                             int* __restrict__ cntOut,
                                             float* __restrict__ dOut, int cap) {
    int row  = blockIdx.x * 8 + (threadIdx.x >> 5);
    int lane = threadIdx.x & 31;
    const unsigned int* brow = bits + (size_t)row * WORDS;

    unsigned w[4]; int c = 0;
    #pragma unroll
    for (int u = 0; u < 4; u++) { w[u] = brow[lane * 4 + u]; c += __popc(w[u]); }

    int inc = c;
    #pragma unroll
    for (int o = 1; o < 32; o <<= 1) {
        int t = __shfl_up_sync(0xffffffffu, inc, o);
        if (lane >= o) inc += t;
    }
    int total = __shfl_sync(0xffffffffu, inc, 31);
    int p = inc - c;

    unsigned short* dst = idxOut + (size_t)row * cap;
    #pragma unroll
    for (int u = 0; u < 4; u++) {
        unsigned word = w[u];
        int base = (lane * 4 + u) * 32;
        while (word) {
            int b = __ffs(word) - 1; word &= word - 1;
            if (p < cap) dst[p] = (unsigned short)(base + b);
            p++;
        }
    }
    if (lane == 31) {
        cntOut[row] = min(total, cap);
        dOut[row]   = rsqrtf((float)total + 1e-8f);
    }
}

__global__ void k_extract1() { extract_body(g_Abits,  g_idx1, g_cnt1, g_d1, CAP1); }
__global__ void k_extract2() { extract_body(g_A2bits, g_idx2, g_cnt2, g_d2, CAP2); }

// ---------------------------------------------------------------------------
// 2-hop mask via neighbor-row union + exact counts at special positions.
// ---------------------------------------------------------------------------
__global__ void k_twohop() {
    __shared__ unsigned s_out[WORDS];
    __shared__ unsigned short s_nb[CAP1];

    const int row = blockIdx.x;
    const int tid = threadIdx.x;   // 128
    const int nj  = g_cnt1[row];

    if (tid < nj) s_nb[tid] = g_idx1[(size_t)row * CAP1 + tid];
    __syncthreads();

    unsigned u = 0;
    for (int e = 0; e < nj; e++) {
        int j = s_nb[e];
        u |= g_Abits[(size_t)j * WORDS + tid];
    }
    unsigned my   = g_Abits[(size_t)row * WORDS + tid];
    unsigned diag = ((row >> 5) == tid) ? (1u << (row & 31)) : 0u;
    s_out[tid] = u & ~my & ~diag;
    __syncthreads();

    if (tid <= nj) {
        int k = (tid < nj) ? s_nb[tid] : row;
        int w = k >> 5, b = k & 31;
        int cnt = 0;
        for (int e = 0; e < nj; e++) {
            int j = s_nb[e];
            cnt += (g_Abits[(size_t)j * WORDS + w] >> b) & 1;
        }
        int abit = (g_Abits[(size_t)row * WORDS + w] >> b) & 1;
        int thr  = abit + (k == row ? 1 : 0);
        if (cnt > thr) atomicOr(&s_out[w], 1u << b);
    }
    __syncthreads();
    g_A2bits[(size_t)row * WORDS + tid] = s_out[tid];
}

// ---------------------------------------------------------------------------
// half4 (8-byte) load -> float4
// ---------------------------------------------------------------------------
__device__ __forceinline__ float4 load_h4(const __half* p) {
    uint2 u = *(const uint2*)p;
    float2 f0 = __half22float2(*(__half2*)&u.x);
    float2 f1 = __half22float2(*(__half2*)&u.y);
    return make_float4(f0.x, f0.y, f1.x, f1.y);
}
__device__ __forceinline__ void acc4(float4& a, float4 v) {
    a.x += v.x; a.y += v.y; a.z += v.z; a.w += v.w;
}

// ---------------------------------------------------------------------------
// Embed GEMM: R0 = relu(X @ We + be); also writes prescaled fp16 P0a/P0b.
// ---------------------------------------------------------------------------
__global__ void k_embed(const float* __restrict__ X, const float* __restrict__ W,
                        const float* __restrict__ bias) {
    __shared__ float As[16][32];
    __shared__ float Bs[16][128];

    const int bm  = blockIdx.x * 32;
    const int tid = threadIdx.x;
    const int tx  = tid & 31;
    const int ty  = tid >> 5;

    float acc[8][4];
    #pragma unroll
    for (int m = 0; m < 8; m++)
        #pragma unroll
        for (int n = 0; n < 4; n++) acc[m][n] = 0.f;

    for (int k0 = 0; k0 < IN_DIM; k0 += 16) {
        {
            int r  = tid >> 2;
            int c4 = tid & 3;
            float4 v = *(const float4*)(X + (size_t)(bm + r) * IN_DIM + k0 + c4 * 4);
            As[c4 * 4 + 0][r] = v.x;
            As[c4 * 4 + 1][r] = v.y;
            As[c4 * 4 + 2][r] = v.z;
            As[c4 * 4 + 3][r] = v.w;
        }
        #pragma unroll
        for (int l = 0; l < 4; l++) {
            int idx = l * 128 + tid;
            int r   = idx >> 5;
            int c4  = idx & 31;
            *(float4*)&Bs[r][c4 * 4] = *(const float4*)(W + (size_t)(k0 + r) * HIDDEN + c4 * 4);
        }
        __syncthreads();

        #pragma unroll
        for (int kk = 0; kk < 16; kk++) {
            float a[8];
            float4 b4 = *(const float4*)&Bs[kk][tx * 4];
            float bb[4] = { b4.x, b4.y, b4.z, b4.w };
            #pragma unroll
            for (int m = 0; m < 8; m++) a[m] = As[kk][ty * 8 + m];
            #pragma unroll
            for (int m = 0; m < 8; m++)
                #pragma unroll
                for (int n = 0; n < 4; n++) acc[m][n] += a[m] * bb[n];
        }
        __syncthreads();
    }

    #pragma unroll
    for (int m = 0; m < 8; m++) {
        int row = bm + ty * 8 + m;
        float d1r = g_d1[row], d2r = g_d2[row];
        #pragma unroll
        for (int n = 0; n < 4; n++) {
            int col = tx * 4 + n;
            float v = acc[m][n] + bias[col];
            v = v > 0.f ? v : 0.f;
            g_R0 [(size_t)row * HIDDEN + col] = v;
            g_P0a[(size_t)row * HIDDEN + col] = __float2half(d1r * v);
            g_P0b[(size_t)row * HIDDEN + col] = __float2half(d2r * v);
        }
    }
}

// ---------------------------------------------------------------------------
// Layer-1 propagation (fused a1+a2). Block=256 (8 warps), row per block.
// Warp w handles neighbors e ≡ w (mod 8); lane owns 4 cols (half4 loads).
// ---------------------------------------------------------------------------
__global__ void k_prop1() {
    __shared__ unsigned short s_i1[CAP1];
    __shared__ unsigned short s_i2[CAP2];
    __shared__ float s_red[8][HIDDEN];     // 4 KB

    const int row = blockIdx.x;
    const int tid = threadIdx.x;
    const int w   = tid >> 5;
    const int l   = tid & 31;
    const int c4  = l * 4;
    const int n1  = g_cnt1[row];
    const int n2  = g_cnt2[row];
    const float d1r = g_d1[row], d2r = g_d2[row];

    for (int e = tid; e < n1; e += 256) s_i1[e] = g_idx1[(size_t)row * CAP1 + e];
    for (int e = tid; e < n2; e += 256) s_i2[e] = g_idx2[(size_t)row * CAP2 + e];
    __syncthreads();

    // ---- phase A : A1 @ R0  (source P0a) ----
    {
        float4 a = {0.f, 0.f, 0.f, 0.f};
        int e = w;
        for (; e + 24 < n1; e += 32) {
            float4 v0 = load_h4(g_P0a + (size_t)s_i1[e     ] * HIDDEN + c4);
            float4 v1 = load_h4(g_P0a + (size_t)s_i1[e +  8] * HIDDEN + c4);
            float4 v2 = load_h4(g_P0a + (size_t)s_i1[e + 16] * HIDDEN + c4);
            float4 v3 = load_h4(g_P0a + (size_t)s_i1[e + 24] * HIDDEN + c4);
            acc4(a, v0); acc4(a, v1); acc4(a, v2); acc4(a, v3);
        }
        for (; e < n1; e += 8) acc4(a, load_h4(g_P0a + (size_t)s_i1[e] * HIDDEN + c4));
        *(float4*)&s_red[w][c4] = a;
    }
    __syncthreads();
    if (tid < HIDDEN) {
        float s = 0.f;
        #pragma unroll
        for (int g = 0; g < 8; g++) s += s_red[g][tid];
        float val = d1r * s;
        g_R1 [(size_t)row * 256 + tid] = val;
        g_P1a[(size_t)row * 256 + tid] = __float2half(d1r * val);
        g_P1b[(size_t)row * 256 + tid] = __float2half(d2r * val);
    }
    __syncthreads();

    // ---- phase B : A2 @ R0  (source P0b) ----
    {
        float4 a = {0.f, 0.f, 0.f, 0.f};
        int e = w;
        for (; e + 24 < n2; e += 32) {
            float4 v0 = load_h4(g_P0b + (size_t)s_i2[e     ] * HIDDEN + c4);
            float4 v1 = load_h4(g_P0b + (size_t)s_i2[e +  8] * HIDDEN + c4);
            float4 v2 = load_h4(g_P0b + (size_t)s_i2[e + 16] * HIDDEN + c4);
            float4 v3 = load_h4(g_P0b + (size_t)s_i2[e + 24] * HIDDEN + c4);
            acc4(a, v0); acc4(a, v1); acc4(a, v2); acc4(a, v3);
        }
        for (; e < n2; e += 8) acc4(a, load_h4(g_P0b + (size_t)s_i2[e] * HIDDEN + c4));
        *(float4*)&s_red[w][c4] = a;
    }
    __syncthreads();
    if (tid < HIDDEN) {
        float s = 0.f;
        #pragma unroll
        for (int g = 0; g < 8; g++) s += s_red[g][tid];
        float val = d2r * s;
        g_R1 [(size_t)row * 256 + 128 + tid] = val;
        g_P1a[(size_t)row * 256 + 128 + tid] = __float2half(d1r * val);
        g_P1b[(size_t)row * 256 + 128 + tid] = __float2half(d2r * val);
    }
}

// ---------------------------------------------------------------------------
// Layer-2 propagation (fused a1+a2). Block=256 = 4 groups x 64 threads.
// Group g handles neighbors e ≡ g (mod 4); thread owns 4 of 256 cols.
// ---------------------------------------------------------------------------
__global__ void k_prop2() {
    __shared__ unsigned short s_i1[CAP1];
    __shared__ unsigned short s_i2[CAP2];
    __shared__ float s_red[4][2 * HIDDEN]; // 4 KB

    const int row = blockIdx.x;
    const int tid = threadIdx.x;
    const int g   = tid >> 6;
    const int t   = tid & 63;
    const int c4  = t * 4;
    const int n1  = g_cnt1[row];
    const int n2  = g_cnt2[row];
    const float d1r = g_d1[row], d2r = g_d2[row];

    for (int e = tid; e < n1; e += 256) s_i1[e] = g_idx1[(size_t)row * CAP1 + e];
    for (int e = tid; e < n2; e += 256) s_i2[e] = g_idx2[(size_t)row * CAP2 + e];
    __syncthreads();

    // ---- phase A : A1 @ R1  (source P1a) ----
    {
        float4 a = {0.f, 0.f, 0.f, 0.f};
        int e = g;
        for (; e + 12 < n1; e += 16) {
            float4 v0 = load_h4(g_P1a + (size_t)s_i1[e     ] * 256 + c4);
            float4 v1 = load_h4(g_P1a + (size_t)s_i1[e +  4] * 256 + c4);
            float4 v2 = load_h4(g_P1a + (size_t)s_i1[e +  8] * 256 + c4);
            float4 v3 = load_h4(g_P1a + (size_t)s_i1[e + 12] * 256 + c4);
            acc4(a, v0); acc4(a, v1); acc4(a, v2); acc4(a, v3);
        }
        for (; e < n1; e += 4) acc4(a, load_h4(g_P1a + (size_t)s_i1[e] * 256 + c4));
        *(float4*)&s_red[g][c4] = a;
    }
    __syncthreads();
    {
        float s = s_red[0][tid] + s_red[1][tid] + s_red[2][tid] + s_red[3][tid];
        g_R2[(size_t)row * 512 + tid] = d1r * s;
    }
    __syncthreads();

    // ---- phase B : A2 @ R1  (source P1b) ----
    {
        float4 a = {0.f, 0.f, 0.f, 0.f};
        int e = g;
        for (; e + 12 < n2; e += 16) {
            float4 v0 = load_h4(g_P1b + (size_t)s_i2[e     ] * 256 + c4);
            float4 v1 = load_h4(g_P1b + (size_t)s_i2[e +  4] * 256 + c4);
            float4 v2 = load_h4(g_P1b + (size_t)s_i2[e +  8] * 256 + c4);
            float4 v3 = load_h4(g_P1b + (size_t)s_i2[e + 12] * 256 + c4);
            acc4(a, v0); acc4(a, v1); acc4(a, v2); acc4(a, v3);
        }
        for (; e < n2; e += 4) acc4(a, load_h4(g_P1b + (size_t)s_i2[e] * 256 + c4));
        *(float4*)&s_red[g][c4] = a;
    }
    __syncthreads();
    {
        float s = s_red[0][tid] + s_red[1][tid] + s_red[2][tid] + s_red[3][tid];
        g_R2[(size_t)row * 512 + 256 + tid] = d2r * s;
    }
}

// ---------------------------------------------------------------------------
// classifier
// ---------------------------------------------------------------------------
__global__ void k_final(const float* __restrict__ Wc, const float* __restrict__ bc,
                        float* __restrict__ out) {
    int row  = blockIdx.x * 8 + (threadIdx.x >> 5);
    int lane = threadIdx.x & 31;

    float acc[NUM_CLASSES];
    #pragma unroll
    for (int cc = 0; cc < NUM_CLASSES; cc++) acc[cc] = 0.f;

    for (int j = lane; j < FINAL_DIM; j += 32) {
        float x;
        if (j < 128)       x = g_R0[(size_t)row * 128 + j];
        else if (j < 384)  x = g_R1[(size_t)row * 256 + (j - 128)];
        else               x = g_R2[(size_t)row * 512 + (j - 384)];
        const float* wr = Wc + (size_t)j * NUM_CLASSES;
        #pragma unroll
        for (int cc = 0; cc < NUM_CLASSES; cc++) acc[cc] += x * wr[cc];
    }
    #pragma unroll
    for (int cc = 0; cc < NUM_CLASSES; cc++)
        #pragma unroll
        for (int o = 16; o; o >>= 1) acc[cc] += __shfl_xor_sync(0xffffffffu, acc[cc], o);

    if (lane == 0) {
        #pragma unroll
        for (int cc = 0; cc < NUM_CLASSES; cc++)
            out[(size_t)row * NUM_CLASSES + cc] = acc[cc] + bc[cc];
    }
}

// ---------------------------------------------------------------------------
// launch — pure kernel launches
// ---------------------------------------------------------------------------
extern "C" void kernel_launch(void* const* d_in, const int* in_sizes, int n_in,
                              void* d_out, int out_size) {
    const float* X  = (const float*)d_in[0];
    const int*   E  = (const int*)d_in[1];          // int32 (jax x64 disabled)
    const float* We = (const float*)d_in[2];
    const float* be = (const float*)d_in[3];
    const float* Wc = (const float*)d_in[4];
    const float* bc = (const float*)d_in[5];
    float* out = (float*)d_out;

    k_zero_bits<<<(N_NODES * WORDS + 255) / 256, 256>>>();
    k_scatter<<<N_EDGES / 256, 256>>>(E);
    k_extract1<<<N_NODES / 8, 256>>>();
    k_twohop<<<N_NODES, 128>>>();
    k_extract2<<<N_NODES / 8, 256>>>();

    k_embed<<<N_NODES / 32, 128>>>(X, We, be);

    k_prop1<<<N_NODES, 256>>>();
    k_prop2<<<N_NODES, 256>>>();

    k_final<<<N_NODES / 8, 256>>>(Wc, bc, out);
}